// round 11
// baseline (speedup 1.0000x reference)
#include <cuda_runtime.h>

// 24 sparse multilinear coefficients (Pauli-propagation sparsity, validated
// R6/R8/R9/R10):
//  [0..7]  out0(x0,x1,x3), [8..15] out1(x0,x2,x3),
//  [16..19] out2(x1,x3),   [20..23] out3(x0,x2)
__device__ __align__(16) float g_P[24];

// ---------------------------------------------------------------------------
// Prep kernel (1 block, 256 threads): shuffle-based circuit sim + 24 coeffs.
// Signals PDL completion as soon as g_P is globally visible.
// ---------------------------------------------------------------------------
__global__ void prep_kernel(const float* __restrict__ weights) {
    __shared__ float shWre[16][16];   // [j][col]
    __shared__ float shWim[16][16];
    __shared__ float sPart[24][8];
    const int tid = threadIdx.x;
    const unsigned FULL = 0xffffffffu;

    // ---- Phase 1: one amplitude per thread, shfl butterflies ----
    {
        const int col = tid >> 4;
        const int j   = tid & 15;

        float re = (j == col) ? 1.f : 0.f;
        float im = 0.f;

#pragma unroll
        for (int l = 0; l < 2; l++) {
#pragma unroll
            for (int w = 0; w < 4; w++) {
                const float th = weights[l * 4 + w] * 0.5f;
                float c, s;
                __sincosf(th, &s, &c);
                const int bit = 8 >> w;
                const float pre = __shfl_xor_sync(FULL, re, bit);
                const float pim = __shfl_xor_sync(FULL, im, bit);
                const float nre = fmaf(c, re,  s * pim);
                const float nim = fmaf(c, im, -s * pre);
                re = nre; im = nim;
            }
#pragma unroll
            for (int w = 0; w < 4; w++) {
                const int cb = 8 >> w;
                const int tb = 8 >> ((w + 1) & 3);
                const int srcj = (j & cb) ? (j ^ tb) : j;
                const int srclane = (tid & 16) | srcj;
                re = __shfl_sync(FULL, re, srclane);
                im = __shfl_sync(FULL, im, srclane);
            }
        }

        const int pc = __popc(col) & 3;
        float wre, wim;
        if (pc == 0)      { wre = re;   wim = im;  }
        else if (pc == 1) { wre = im;   wim = -re; }
        else if (pc == 2) { wre = -re;  wim = -im; }
        else              { wre = -im;  wim = re;  }
        shWre[j][col] = wre;
        shWim[j][col] = wim;
    }
    __syncthreads();

    // ---- Phase 2: 24 coefficients x 8 partials ----
    if (tid < 192) {
        const int coef = tid >> 3;
        const int part = tid & 7;

        int w, a, b, c, d;
        if (coef < 8)       { w = 0; a = (coef >> 2) + 1; b = ((coef >> 1) & 1) + 1; c = 0; d = (coef & 1) + 1; }
        else if (coef < 16) { int r = coef - 8;  w = 1; a = (r >> 2) + 1; b = 0; c = ((r >> 1) & 1) + 1; d = (r & 1) + 1; }
        else if (coef < 20) { int r = coef - 16; w = 2; a = 0; b = (r >> 1) + 1; c = 0; d = (r & 1) + 1; }
        else                { int r = coef - 20; w = 3; a = (r >> 1) + 1; b = 0; c = (r & 1) + 1; d = 0; }

        int m1 = 0, m2 = 0;
        if (a == 1) m1 |= 8; else if (a == 2) m2 |= 8;
        if (b == 1) m1 |= 4; else if (b == 2) m2 |= 4;
        if (c == 1) m1 |= 2; else if (c == 2) m2 |= 2;
        if (d == 1) m1 |= 1; else if (d == 2) m2 |= 1;

        const int bitpos = 3 - w;
        float sum = 0.f;
#pragma unroll
        for (int xo = 0; xo < 2; xo++) {
            const int x = part * 2 + xo;
            const int y = x ^ m2;
            const float sgn1 = (__popc(x & m1) & 1) ? -1.f : 1.f;
            float acc = 0.f;
#pragma unroll
            for (int j = 0; j < 16; j++) {
                const float sgn2 = ((j >> bitpos) & 1) ? -1.f : 1.f;
                acc += sgn2 * (shWre[j][x] * shWre[j][y] + shWim[j][x] * shWim[j][y]);
            }
            sum += sgn1 * acc;
        }
        sPart[coef][part] = sum;
    }
    __syncthreads();

    if (tid < 24) {
        float s = 0.f;
#pragma unroll
        for (int p = 0; p < 8; p++) s += sPart[tid][p];
        g_P[tid] = s * 0.0625f;
    }
    __threadfence();     // make g_P globally visible before signaling
    __syncthreads();
#if __CUDA_ARCH__ >= 900
    cudaTriggerProgrammaticLaunchCompletion();
#endif
}

// ---------------------------------------------------------------------------
// Main kernel (PDL consumer): front-load x-load + all sincos (independent of
// P), then wait on the prep grid, then read P and finish.
// ---------------------------------------------------------------------------
__global__ __launch_bounds__(256) void qenc_main_kernel(
    const float4* __restrict__ x4, float4* __restrict__ out4, int n)
{
    const int i = blockIdx.x * 256 + threadIdx.x;
    if (i >= n) {
#if __CUDA_ARCH__ >= 900
        cudaGridDependencySynchronize();
#endif
        return;
    }

    const float4 xv = x4[i];
    float c0, s0, c1, s1, c2, s2, c3, s3;
    __sincosf(xv.x, &s0, &c0);
    __sincosf(xv.y, &s1, &c1);
    __sincosf(xv.z, &s2, &c2);
    __sincosf(xv.w, &s3, &c3);

#if __CUDA_ARCH__ >= 900
    cudaGridDependencySynchronize();   // prep's g_P now visible
#endif

    float P[24];
    {
        const float4* Pg = (const float4*)g_P;
#pragma unroll
        for (int k = 0; k < 6; k++) {
            const float4 v = __ldg(&Pg[k]);
            P[4 * k + 0] = v.x; P[4 * k + 1] = v.y;
            P[4 * k + 2] = v.z; P[4 * k + 3] = v.w;
        }
    }

    // out0: wires 0,1,3
    float a1 = fmaf(P[1], s3, P[0] * c3);
    float a2 = fmaf(P[3], s3, P[2] * c3);
    float a3 = fmaf(P[5], s3, P[4] * c3);
    float a4 = fmaf(P[7], s3, P[6] * c3);
    float u1 = fmaf(a2, s1, a1 * c1);
    float u2 = fmaf(a4, s1, a3 * c1);
    const float o0 = fmaf(u2, s0, u1 * c0);

    // out1: wires 0,2,3
    float b1 = fmaf(P[9],  s3, P[8]  * c3);
    float b2 = fmaf(P[11], s3, P[10] * c3);
    float b3 = fmaf(P[13], s3, P[12] * c3);
    float b4 = fmaf(P[15], s3, P[14] * c3);
    float v1 = fmaf(b2, s2, b1 * c2);
    float v2 = fmaf(b4, s2, b3 * c2);
    const float o1 = fmaf(v2, s0, v1 * c0);

    // out2: wires 1,3
    float d1 = fmaf(P[17], s3, P[16] * c3);
    float d2 = fmaf(P[19], s3, P[18] * c3);
    const float o2 = fmaf(d2, s1, d1 * c1);

    // out3: wires 0,2
    float e1 = fmaf(P[21], s2, P[20] * c2);
    float e2 = fmaf(P[23], s2, P[22] * c2);
    const float o3 = fmaf(e2, s0, e1 * c0);

    out4[i] = make_float4(o0, o1, o2, o3);
}

extern "C" void kernel_launch(void* const* d_in, const int* in_sizes, int n_in,
                              void* d_out, int out_size) {
    const float* x = (const float*)d_in[0];        // [B, 4] float32
    const float* weights = (const float*)d_in[1];  // [2, 4] float32
    float* out = (float*)d_out;                    // [B, 4] float32

    const int n = in_sizes[0] / 4;
    const int grid = (n + 255) / 256;

    prep_kernel<<<1, 256>>>(weights);

    // PDL launch: main may begin while prep runs; cudaGridDependencySynchronize
    // inside main provides the ordering on g_P.
    cudaLaunchConfig_t cfg = {};
    cfg.gridDim = dim3(grid, 1, 1);
    cfg.blockDim = dim3(256, 1, 1);
    cfg.dynamicSmemBytes = 0;
    cfg.stream = 0;
    cudaLaunchAttribute attrs[1];
    attrs[0].id = cudaLaunchAttributeProgrammaticStreamSerialization;
    attrs[0].val.programmaticStreamSerializationAllowed = 1;
    cfg.attrs = attrs;
    cfg.numAttrs = 1;

    cudaError_t err = cudaLaunchKernelEx(&cfg, qenc_main_kernel,
                                         (const float4*)x, (float4*)out, n);
    if (err != cudaSuccess) {
        // Fallback: plain serialized launch (still correct).
        qenc_main_kernel<<<grid, 256>>>((const float4*)x, (float4*)out, n);
    }
}

// round 12
// speedup vs baseline: 1.4337x; 1.4337x over previous
#include <cuda_runtime.h>

// ---------------------------------------------------------------------------
// Closed-form kernel (Heisenberg / Pauli propagation of Z_w through the
// circuit; all X-bearing strings vanish in the RX product state):
//   z_w   = cos(x_w + theta0_w)
//   out0  = C11*C12*C13 * z0*z1*z3
//   out1  = C10*C11     * z0*z2*z3
//   out2  = C10*C11*C12 * z1*z3
//   out3  = C10*C11*C12*C13 * z0*z2
// where C1w = cos(theta1_w). Matches the validated rank-1 structure of the
// R6-R11 numeric coefficients.
// ---------------------------------------------------------------------------
__global__ __launch_bounds__(256) void qenc_kernel(
    const float* __restrict__ weights,
    const float4* __restrict__ x4,
    float4* __restrict__ out4,
    int n)
{
    const int i = blockIdx.x * 256 + threadIdx.x;
    if (i >= n) return;

    // Weight-derived constants (uniform; broadcast L1 loads + 4 MUFU).
    const float4 w0 = __ldg((const float4*)weights);       // theta0_{0..3}
    const float4 w1 = __ldg((const float4*)(weights + 4)); // theta1_{0..3}
    const float C10 = __cosf(w1.x);
    const float C11 = __cosf(w1.y);
    const float C12 = __cosf(w1.z);
    const float C13 = __cosf(w1.w);
    const float K0 = C11 * C12 * C13;
    const float K1 = C10 * C11;
    const float K2 = K1 * C12;
    const float K3 = K2 * C13;

    const float4 xv = x4[i];
    const float z0 = __cosf(xv.x + w0.x);
    const float z1 = __cosf(xv.y + w0.y);
    const float z2 = __cosf(xv.z + w0.z);
    const float z3 = __cosf(xv.w + w0.w);

    const float p03 = z0 * z3;
    const float o0 = K0 * z1 * p03;
    const float o1 = K1 * z2 * p03;
    const float o2 = K2 * (z1 * z3);
    const float o3 = K3 * (z0 * z2);

    out4[i] = make_float4(o0, o1, o2, o3);
}

extern "C" void kernel_launch(void* const* d_in, const int* in_sizes, int n_in,
                              void* d_out, int out_size) {
    const float* x = (const float*)d_in[0];        // [B, 4] float32
    const float* weights = (const float*)d_in[1];  // [2, 4] float32
    float* out = (float*)d_out;                    // [B, 4] float32

    const int n = in_sizes[0] / 4;

    qenc_kernel<<<(n + 255) / 256, 256>>>(
        weights, (const float4*)x, (float4*)out, n);
}

// round 13
// speedup vs baseline: 1.4815x; 1.0333x over previous
#include <cuda_runtime.h>

// ---------------------------------------------------------------------------
// Exact closed form via Heisenberg/Pauli propagation (full enumeration of
// surviving Pauli strings; X-free survivors only):
//   F_w = cos(x_w + th0_w), G_w = sin(x_w + th0_w)
//   c_w = cos(th1_w),        s_w = sin(th1_w)
//   out0 = c1c2c3 F0F1F3 + c1c2s3 G0G1G3 + s1s2c3 F0G1G3 + s1s2s3 G0F1F3
//   out1 = c0c1 F0F2F3 + s0s1 G0G2F3
//   out2 = c0c1c2 F1F3 + c0s1s2 G1G3
//   out3 = c0c1c2c3 F0F2 + s0s1c2c3 G0G2 + c0s1s2s3 G0F2
// Two samples per thread (MLP=2), both coalesced.
// ---------------------------------------------------------------------------
__global__ __launch_bounds__(256) void qenc_kernel(
    const float* __restrict__ weights,
    const float4* __restrict__ x4,
    float4* __restrict__ out4,
    int n, int half)
{
    const int iA = blockIdx.x * 256 + threadIdx.x;
    if (iA >= half) return;
    const int iB = iA + half;
    const bool hasB = (iB < n);

    // Uniform weight-derived constants (broadcast loads + 8 MUFU).
    const float4 w0 = __ldg((const float4*)weights);       // th0_{0..3}
    const float4 w1 = __ldg((const float4*)(weights + 4)); // th1_{0..3}
    float c0w, s0w, c1w, s1w, c2w, s2w, c3w, s3w;
    __sincosf(w1.x, &s0w, &c0w);
    __sincosf(w1.y, &s1w, &c1w);
    __sincosf(w1.z, &s2w, &c2w);
    __sincosf(w1.w, &s3w, &c3w);

    // out0 coefficients
    const float A0 = c1w * c2w * c3w;   // F0F1F3
    const float A1 = c1w * c2w * s3w;   // G0G1G3
    const float A2 = s1w * s2w * c3w;   // F0G1G3
    const float A3 = s1w * s2w * s3w;   // G0F1F3
    // out1
    const float B0 = c0w * c1w;         // F0F2F3
    const float B1 = s0w * s1w;         // G0G2F3
    // out2
    const float C0 = c0w * c1w * c2w;   // F1F3
    const float C1 = c0w * s1w * s2w;   // G1G3
    // out3
    const float D0 = C0 * c3w;          // F0F2
    const float D1 = s0w * s1w * c2w * c3w; // G0G2
    const float D2 = c0w * s1w * s2w * s3w; // G0F2

    const float4 xa = x4[iA];
    const float4 xb = hasB ? x4[iB] : xa;

#pragma unroll
    for (int pass = 0; pass < 2; pass++) {
        if (pass == 1 && !hasB) break;
        const float4 xv = (pass == 0) ? xa : xb;

        float F0, G0, F1, G1, F2, G2, F3, G3;
        __sincosf(xv.x + w0.x, &G0, &F0);
        __sincosf(xv.y + w0.y, &G1, &F1);
        __sincosf(xv.z + w0.z, &G2, &F2);
        __sincosf(xv.w + w0.w, &G3, &F3);

        const float F0F3 = F0 * F3, G0G3 = G0 * G3;
        const float F0G3 = F0 * G3, G0F3 = G0 * F3;

        const float o0 = fmaf(A0 * F1, F0F3,
                         fmaf(A1 * G1, G0G3,
                         fmaf(A2 * G1, F0G3, A3 * F1 * G0F3)));
        const float o1 = fmaf(B0 * F2, F0F3, B1 * G2 * G0F3);
        const float o2 = fmaf(C0, F1 * F3, C1 * (G1 * G3));
        const float o3 = fmaf(D0, F0 * F2, fmaf(D1, G0 * G2, D2 * (G0 * F2)));

        out4[(pass == 0) ? iA : iB] = make_float4(o0, o1, o2, o3);
    }
}

extern "C" void kernel_launch(void* const* d_in, const int* in_sizes, int n_in,
                              void* d_out, int out_size) {
    const float* x = (const float*)d_in[0];        // [B, 4] float32
    const float* weights = (const float*)d_in[1];  // [2, 4] float32
    float* out = (float*)d_out;                    // [B, 4] float32

    const int n = in_sizes[0] / 4;
    const int half = (n + 1) / 2;

    qenc_kernel<<<(half + 255) / 256, 256>>>(
        weights, (const float4*)x, (float4*)out, n, half);
}